// round 8
// baseline (speedup 1.0000x reference)
#include <cuda_runtime.h>
#include <cstdint>

// Problem constants (fixed shapes from setup_inputs)
#define Bb   16
#define Cc   256
#define Hh   80
#define Ww_  256
#define HW_  20480      // Hh*Ww_
#define Tt   128
#define T1   129        // T + time token
#define TP   144        // padded T (16*9)
#define ASTR 258        // attn smem row stride (floats)

// ---------------- static device scratch (no allocation) ----------------
__device__ float g_mean[Bb*Cc];
__device__ float g_rstd[Bb*Cc];
__device__ float g_AT [Cc*Cc];                 // AT[cp][c] = (WqT Wk /16)[c][cp]
__device__ float g_BmT[Cc*Cc];                 // BmT[c][e] = (Wl Wv)[e][c]
__device__ float g_kk2T[(size_t)Bb*Cc*TP];     // [b][c][t]
__device__ float g_vv  [(size_t)Bb*TP*Cc];     // [b][t][e]
__device__ float g_bias[Bb*TP];

// ---------------- f32x2 helpers ----------------
__device__ __forceinline__ unsigned long long pk2(float lo, float hi) {
    unsigned long long r;
    asm("mov.b64 %0, {%1,%2};" : "=l"(r) : "f"(lo), "f"(hi));
    return r;
}
__device__ __forceinline__ float2 upk2(unsigned long long v) {
    float2 r;
    asm("mov.b64 {%0,%1}, %2;" : "=f"(r.x), "=f"(r.y) : "l"(v));
    return r;
}
#define FFMA2(d, a, b) asm("fma.rn.f32x2 %0, %1, %2, %0;" : "+l"(d) : "l"(a), "l"(b))
__device__ __forceinline__ unsigned long long mul2(unsigned long long a, unsigned long long b) {
    unsigned long long d;
    asm("mul.rn.f32x2 %0, %1, %2;" : "=l"(d) : "l"(a), "l"(b));
    return d;
}

// ================= Kernel 1: per-(b,c) instance-norm stats =================
__global__ void k_stats(const float* __restrict__ x) {
    int bc = blockIdx.x;                 // b*Cc + c
    int tid = threadIdx.x;
    const float4* xp = (const float4*)(x + (size_t)bc * HW_);
    float s = 0.f, s2 = 0.f;
    for (int i = tid; i < HW_/4; i += 256) {
        float4 v = xp[i];
        s  += v.x + v.y + v.z + v.w;
        s2 += v.x*v.x + v.y*v.y + v.z*v.z + v.w*v.w;
    }
    __shared__ float rs[256], rq[256];
    rs[tid] = s; rq[tid] = s2;
    __syncthreads();
    for (int st = 128; st > 0; st >>= 1) {
        if (tid < st) { rs[tid] += rs[tid+st]; rq[tid] += rq[tid+st]; }
        __syncthreads();
    }
    if (tid == 0) {
        float mean = rs[0] * (1.0f / HW_);
        float var  = rq[0] * (1.0f / HW_) - mean * mean;
        g_mean[bc] = mean;
        g_rstd[bc] = rsqrtf(var + 1e-5f);
    }
}

// ================= Kernel 2a: AT[i][j] = (1/16) * sum_d Wk[d][i]*Wq[d][j] =================
__global__ void k_prepAT(const float* __restrict__ Wq, const float* __restrict__ Wk) {
    __shared__ float As[16][17], Bs[16][17];
    int i0 = blockIdx.y * 16, j0 = blockIdx.x * 16;
    int ty = threadIdx.y, tx = threadIdx.x;
    float acc = 0.f;
    for (int kt = 0; kt < Cc; kt += 16) {
        As[ty][tx] = Wk[(kt+ty)*Cc + i0 + tx];
        Bs[ty][tx] = Wq[(kt+ty)*Cc + j0 + tx];
        __syncthreads();
        #pragma unroll
        for (int kk = 0; kk < 16; kk++) acc += As[kk][ty] * Bs[kk][tx];
        __syncthreads();
    }
    g_AT[(i0+ty)*Cc + j0 + tx] = acc * 0.0625f;
}

// ================= Kernel 2b: BmT[c][e] = sum_d Wv[d][c]*Wl[e][d] =================
__global__ void k_prepBmT(const float* __restrict__ Wl, const float* __restrict__ Wv) {
    __shared__ float Vs[16][17], Ls[16][17];
    int c0 = blockIdx.y * 16, e0 = blockIdx.x * 16;
    int ty = threadIdx.y, tx = threadIdx.x;
    float acc = 0.f;
    for (int dt = 0; dt < Cc; dt += 16) {
        Vs[ty][tx] = Wv[(dt+ty)*Cc + c0 + tx];
        Ls[ty][tx] = Wl[(e0+ty)*Cc + dt + tx];   // Ls[e_local][d_local]
        __syncthreads();
        #pragma unroll
        for (int dd = 0; dd < 16; dd++) acc += Vs[dd][ty] * Ls[tx][dd];
        __syncthreads();
    }
    g_BmT[(c0+ty)*Cc + e0 + tx] = acc;
}

// ================= Kernel 3: style projections kk2T / vv / bias =================
// One block per t (144 blocks), loops all 16 batches, 256 threads (=c or e).
__global__ void k_styproj(const float* __restrict__ sty,
                          const float* __restrict__ timev,
                          const float* __restrict__ sty_mask) {
    int t = blockIdx.x;          // 0..TP-1
    int c = threadIdx.x;         // 0..255
    bool pad = (t >= T1);
    __shared__ float ss[Bb][Cc];
    __shared__ float red[256];

    if (!pad) {
        for (int b = 0; b < Bb; b++)
            ss[b][c] = (t == 0) ? timev[b*Cc + c]
                                : sty[((size_t)b*Cc + c)*Tt + (t-1)];
    }
    __syncthreads();

    float kk[Bb], vv[Bb];
    #pragma unroll
    for (int b = 0; b < Bb; b++) { kk[b] = 0.f; vv[b] = 0.f; }

    if (!pad) {
        for (int cp = 0; cp < Cc; cp++) {
            float a  = g_AT [cp*Cc + c];
            float bm = g_BmT[cp*Cc + c];
            #pragma unroll
            for (int b = 0; b < Bb; b++) {
                float s = ss[b][cp];
                kk[b] = fmaf(a,  s, kk[b]);
                vv[b] = fmaf(bm, s, vv[b]);
            }
        }
    }

    for (int b = 0; b < Bb; b++) {
        float r  = g_rstd[b*Cc + c];
        float mu = g_mean[b*Cc + c];
        bool masked = false;
        if (!pad && t > 0) masked = (sty_mask[b*Tt + (t-1)] == 0.0f);
        float kk2 = (pad || masked) ? 0.f : kk[b] * r;

        red[c] = mu * kk2;
        __syncthreads();
        for (int st = 128; st > 0; st >>= 1) {
            if (c < st) red[c] += red[c+st];
            __syncthreads();
        }
        if (c == 0) {
            float bias = pad ? -1e30f : (masked ? -10000.0f : -red[0]);
            g_bias[b*TP + t] = bias;
        }
        g_kk2T[((size_t)b*Cc + c)*TP + t] = kk2;
        g_vv  [((size_t)b*TP + t)*Cc + c] = pad ? 0.f : vv[b];
        __syncthreads();
    }
}

// ================= Kernel 4: fused attention main kernel =================
// Grid: (Hh=80, Bb=16). Block: 256 threads. 256 pixels (one full W row) per CTA.
// Thread map: ty = tid&15 (t-group: t in [ty*9, ty*9+9) ; e = j*16+ty),
//             tx = tid>>4 (16 px: [tx*16, tx*16+16)).
// Dynamic smem layout (floats):
//   attn [TP][ASTR]                      : 144*258 = 37152
//   stage (union)                        : 4608   (GEMM1: xs[8][256]+ksd[8][288]; GEMM2: vvd[16][256])
//   biasv[144], xm[256]                  : 400
#define SM_STAGE_OFF  (TP*ASTR)
#define SM_BIAS_OFF   (SM_STAGE_OFF + 4608)
#define SM_XM_OFF     (SM_BIAS_OFF + 144)
#define SM_FLOATS     (SM_XM_OFF + 256)

__global__ void __launch_bounds__(256, 1)
k_main(const float* __restrict__ x, const float* __restrict__ xmask,
       float* __restrict__ y) {
    extern __shared__ float smem[];
    float* attn  = smem;
    float* stage = smem + SM_STAGE_OFF;
    float* ksd   = stage + 2048;
    float* biasv = smem + SM_BIAS_OFF;
    float* xm    = smem + SM_XM_OFF;

    const int tile = blockIdx.x;      // h row
    const int b    = blockIdx.y;
    const int tid  = threadIdx.x;
    const int ty   = tid & 15;
    const int tx   = tid >> 4;
    const int p0   = tile * 256;

    // preload bias + x_mask row
    if (tid < TP) biasv[tid] = g_bias[b*TP + tid];
    xm[tid] = xmask[b*Ww_ + tid];
    __syncthreads();

    // -------- GEMM1: logits[px][t] = sum_c x[c][px]*kk2[c][t] + bias[t] --------
    unsigned long long acc[8][9];
    #pragma unroll
    for (int j = 0; j < 9; j++) {
        float bv = biasv[ty*9 + j];
        unsigned long long bp = pk2(bv, bv);
        #pragma unroll
        for (int i = 0; i < 8; i++) acc[i][j] = bp;
    }

    const float* xb = x + (size_t)b * Cc * HW_ + p0;
    const float* kb = g_kk2T + (size_t)b * Cc * TP;

    for (int c0 = 0; c0 < Cc; c0 += 8) {
        __syncthreads();
        // stage x: 8 rows x 256 px
        for (int i = tid; i < 512; i += 256) {
            int cc = i >> 6, pq = i & 63;
            ((float4*)stage)[i] = *(const float4*)(xb + (size_t)(c0+cc)*HW_ + (pq<<2));
        }
        // stage kk2 rows, duplicated pairs for f32x2
        if (tid < TP) {
            #pragma unroll
            for (int cc = 0; cc < 8; cc++) {
                float v = kb[(size_t)(c0+cc)*TP + tid];
                *(float2*)&ksd[cc*288 + 2*tid] = make_float2(v, v);
            }
        }
        __syncthreads();

        #pragma unroll
        for (int cc = 0; cc < 8; cc++) {
            const float* xr = stage + cc*256 + tx*16;
            unsigned long long xv[8];
            #pragma unroll
            for (int i = 0; i < 8; i++)
                xv[i] = *(const unsigned long long*)(xr + 2*i);
            const float* kr = ksd + cc*288 + 2*(ty*9);
            #pragma unroll
            for (int j = 0; j < 9; j++) {
                unsigned long long kv = *(const unsigned long long*)(kr + 2*j);
                #pragma unroll
                for (int i = 0; i < 8; i++) FFMA2(acc[i][j], xv[i], kv);
            }
        }
    }

    // -------- softmax over t (144), cross-thread via shfl within 16-lane groups --------
    float mx[16];
    #pragma unroll
    for (int i = 0; i < 16; i++) mx[i] = -3.4e38f;
    #pragma unroll
    for (int i = 0; i < 8; i++)
        #pragma unroll
        for (int j = 0; j < 9; j++) {
            float2 v = upk2(acc[i][j]);
            mx[2*i]   = fmaxf(mx[2*i],   v.x);
            mx[2*i+1] = fmaxf(mx[2*i+1], v.y);
        }
    #pragma unroll
    for (int s = 1; s < 16; s <<= 1)
        #pragma unroll
        for (int i = 0; i < 16; i++)
            mx[i] = fmaxf(mx[i], __shfl_xor_sync(0xffffffffu, mx[i], s));

    float sm[16];
    #pragma unroll
    for (int i = 0; i < 16; i++) sm[i] = 0.f;
    #pragma unroll
    for (int j = 0; j < 9; j++) {
        float* arow = attn + (ty*9 + j)*ASTR + tx*16;
        #pragma unroll
        for (int i = 0; i < 8; i++) {
            float2 v = upk2(acc[i][j]);
            float e0 = __expf(v.x - mx[2*i]);
            float e1 = __expf(v.y - mx[2*i+1]);
            sm[2*i]   += e0;
            sm[2*i+1] += e1;
            *(float2*)(arow + 2*i) = make_float2(e0, e1);
        }
    }
    #pragma unroll
    for (int s = 1; s < 16; s <<= 1)
        #pragma unroll
        for (int i = 0; i < 16; i++)
            sm[i] += __shfl_xor_sync(0xffffffffu, sm[i], s);

    unsigned long long rsp[8];
    #pragma unroll
    for (int i = 0; i < 8; i++)
        rsp[i] = pk2(1.0f / sm[2*i], 1.0f / sm[2*i+1]);

    // -------- GEMM2 + epilogue: out[px][e] = (sum_t p*vv) * rsum; y = (x+out)*mask --------
    const float* vvb = g_vv + (size_t)b * TP * Cc;
    const size_t rowb = (size_t)b * Cc;

    for (int h = 0; h < 2; h++) {
        unsigned long long a2[8][8];
        #pragma unroll
        for (int i = 0; i < 8; i++)
            #pragma unroll
            for (int j = 0; j < 8; j++) a2[i][j] = 0ULL;

        for (int tc = 0; tc < 9; tc++) {
            __syncthreads();
            // stage vvd[16][256]: vv rows tc*16..+15, e' = 0..127 of this half, duplicated
            for (int i = tid; i < 2048; i += 256) {
                int tt = i >> 7, ep = i & 127;
                float v = vvb[(size_t)(tc*16 + tt)*Cc + h*128 + ep];
                *(float2*)&stage[tt*256 + 2*ep] = make_float2(v, v);
            }
            __syncthreads();

            #pragma unroll 4
            for (int tt = 0; tt < 16; tt++) {
                const float* arow = attn + (tc*16 + tt)*ASTR + tx*16;
                unsigned long long ap[8];
                #pragma unroll
                for (int i = 0; i < 8; i++)
                    ap[i] = *(const unsigned long long*)(arow + 2*i);
                const float* vr = stage + tt*256 + 2*ty;
                #pragma unroll
                for (int j = 0; j < 8; j++) {
                    unsigned long long vp = *(const unsigned long long*)(vr + j*32);
                    #pragma unroll
                    for (int i = 0; i < 8; i++) FFMA2(a2[i][j], ap[i], vp);
                }
            }
        }

        // epilogue for this half: e = (h*8 + j)*16 + ty
        #pragma unroll
        for (int j = 0; j < 8; j++) {
            int e = (h*8 + j)*16 + ty;
            const float* xr = x + (rowb + e)*HW_ + p0 + tx*16;
            float*       yr = y + (rowb + e)*HW_ + p0 + tx*16;
            #pragma unroll
            for (int q = 0; q < 4; q++) {
                float2 o0 = upk2(mul2(a2[2*q  ][j], rsp[2*q  ]));
                float2 o1 = upk2(mul2(a2[2*q+1][j], rsp[2*q+1]));
                float4 xv = *(const float4*)(xr + 4*q);
                float4 m4 = *(const float4*)&xm[tx*16 + 4*q];
                float4 r;
                r.x = (xv.x + o0.x) * m4.x;
                r.y = (xv.y + o0.y) * m4.y;
                r.z = (xv.z + o1.x) * m4.z;
                r.w = (xv.w + o1.y) * m4.w;
                *(float4*)(yr + 4*q) = r;
            }
        }
    }
}

// ================= launch =================
extern "C" void kernel_launch(void* const* d_in, const int* in_sizes, int n_in,
                              void* d_out, int out_size) {
    const float* x        = (const float*)d_in[0];
    const float* x_mask   = (const float*)d_in[1];
    const float* sty      = (const float*)d_in[2];
    const float* sty_mask = (const float*)d_in[3];
    const float* timev    = (const float*)d_in[4];
    const float* Wq       = (const float*)d_in[5];
    const float* Wk       = (const float*)d_in[6];
    const float* Wv       = (const float*)d_in[7];
    const float* Wl       = (const float*)d_in[8];
    float* y = (float*)d_out;

    // stats (independent of prep kernels)
    k_stats<<<Bb*Cc, 256>>>(x);

    // folded weight matrices
    dim3 pb(16, 16), pg(16, 16);
    k_prepAT <<<pg, pb>>>(Wq, Wk);
    k_prepBmT<<<pg, pb>>>(Wl, Wv);

    // style projections (depends on stats + prep; stream-ordered)
    k_styproj<<<TP, 256>>>(sty, timev, sty_mask);

    // main fused kernel
    int smem_bytes = SM_FLOATS * (int)sizeof(float);
    cudaFuncSetAttribute(k_main, cudaFuncAttributeMaxDynamicSharedMemorySize, smem_bytes);
    dim3 grid(Hh, Bb);
    k_main<<<grid, 256, smem_bytes>>>(x, x_mask, y);
}

// round 9
// speedup vs baseline: 1.0006x; 1.0006x over previous
#include <cuda_runtime.h>
#include <cstdint>

// Problem constants (fixed shapes from setup_inputs)
#define Bb   16
#define Cc   256
#define Hh   80
#define Ww_  256
#define HW_  20480      // Hh*Ww_
#define Tt   128
#define T1   129        // T + time token
#define TP   144        // padded T (16*9)
#define ASTR 258        // attn smem row stride (floats)

// ---------------- static device scratch (no allocation) ----------------
__device__ float g_mean[Bb*Cc];
__device__ float g_rstd[Bb*Cc];
__device__ float g_AT [Cc*Cc];                 // AT[cp][c] = (WqT Wk /16)[c][cp]
__device__ float g_BmT[Cc*Cc];                 // BmT[c][e] = (Wl Wv)[e][c]
__device__ float g_kk2T[(size_t)Bb*Cc*TP];     // [b][c][t]
__device__ float g_vv  [(size_t)Bb*TP*Cc];     // [b][t][e]
__device__ float g_bias[Bb*TP];

// ---------------- f32x2 helpers ----------------
__device__ __forceinline__ unsigned long long pk2(float lo, float hi) {
    unsigned long long r;
    asm("mov.b64 %0, {%1,%2};" : "=l"(r) : "f"(lo), "f"(hi));
    return r;
}
__device__ __forceinline__ float2 upk2(unsigned long long v) {
    float2 r;
    asm("mov.b64 {%0,%1}, %2;" : "=f"(r.x), "=f"(r.y) : "l"(v));
    return r;
}
#define FFMA2(d, a, b) asm("fma.rn.f32x2 %0, %1, %2, %0;" : "+l"(d) : "l"(a), "l"(b))
__device__ __forceinline__ unsigned long long mul2(unsigned long long a, unsigned long long b) {
    unsigned long long d;
    asm("mul.rn.f32x2 %0, %1, %2;" : "=l"(d) : "l"(a), "l"(b));
    return d;
}

// ================= Kernel 1: per-(b,c) instance-norm stats =================
__global__ void k_stats(const float* __restrict__ x) {
    int bc = blockIdx.x;                 // b*Cc + c
    int tid = threadIdx.x;
    const float4* xp = (const float4*)(x + (size_t)bc * HW_);
    float s = 0.f, s2 = 0.f;
    for (int i = tid; i < HW_/4; i += 256) {
        float4 v = xp[i];
        s  += v.x + v.y + v.z + v.w;
        s2 += v.x*v.x + v.y*v.y + v.z*v.z + v.w*v.w;
    }
    __shared__ float rs[256], rq[256];
    rs[tid] = s; rq[tid] = s2;
    __syncthreads();
    for (int st = 128; st > 0; st >>= 1) {
        if (tid < st) { rs[tid] += rs[tid+st]; rq[tid] += rq[tid+st]; }
        __syncthreads();
    }
    if (tid == 0) {
        float mean = rs[0] * (1.0f / HW_);
        float var  = rq[0] * (1.0f / HW_) - mean * mean;
        g_mean[bc] = mean;
        g_rstd[bc] = rsqrtf(var + 1e-5f);
    }
}

// ================= Kernel 2a: AT[i][j] = (1/16) * sum_d Wk[d][i]*Wq[d][j] =================
__global__ void k_prepAT(const float* __restrict__ Wq, const float* __restrict__ Wk) {
    __shared__ float As[16][17], Bs[16][17];
    int i0 = blockIdx.y * 16, j0 = blockIdx.x * 16;
    int ty = threadIdx.y, tx = threadIdx.x;
    float acc = 0.f;
    for (int kt = 0; kt < Cc; kt += 16) {
        As[ty][tx] = Wk[(kt+ty)*Cc + i0 + tx];
        Bs[ty][tx] = Wq[(kt+ty)*Cc + j0 + tx];
        __syncthreads();
        #pragma unroll
        for (int kk = 0; kk < 16; kk++) acc += As[kk][ty] * Bs[kk][tx];
        __syncthreads();
    }
    g_AT[(i0+ty)*Cc + j0 + tx] = acc * 0.0625f;
}

// ================= Kernel 2b: BmT[c][e] = sum_d Wv[d][c]*Wl[e][d] =================
__global__ void k_prepBmT(const float* __restrict__ Wl, const float* __restrict__ Wv) {
    __shared__ float Vs[16][17], Ls[16][17];
    int c0 = blockIdx.y * 16, e0 = blockIdx.x * 16;
    int ty = threadIdx.y, tx = threadIdx.x;
    float acc = 0.f;
    for (int dt = 0; dt < Cc; dt += 16) {
        Vs[ty][tx] = Wv[(dt+ty)*Cc + c0 + tx];
        Ls[ty][tx] = Wl[(e0+ty)*Cc + dt + tx];   // Ls[e_local][d_local]
        __syncthreads();
        #pragma unroll
        for (int dd = 0; dd < 16; dd++) acc += Vs[dd][ty] * Ls[tx][dd];
        __syncthreads();
    }
    g_BmT[(c0+ty)*Cc + e0 + tx] = acc;
}

// ================= Kernel 3: style projections kk2T / vv / bias =================
// One block per t (144 blocks), loops all 16 batches, 256 threads (=c or e).
__global__ void k_styproj(const float* __restrict__ sty,
                          const float* __restrict__ timev,
                          const float* __restrict__ sty_mask) {
    int t = blockIdx.x;          // 0..TP-1
    int c = threadIdx.x;         // 0..255
    bool pad = (t >= T1);
    __shared__ float ss[Bb][Cc];
    __shared__ float red[256];

    if (!pad) {
        for (int b = 0; b < Bb; b++)
            ss[b][c] = (t == 0) ? timev[b*Cc + c]
                                : sty[((size_t)b*Cc + c)*Tt + (t-1)];
    }
    __syncthreads();

    float kk[Bb], vv[Bb];
    #pragma unroll
    for (int b = 0; b < Bb; b++) { kk[b] = 0.f; vv[b] = 0.f; }

    if (!pad) {
        for (int cp = 0; cp < Cc; cp++) {
            float a  = g_AT [cp*Cc + c];
            float bm = g_BmT[cp*Cc + c];
            #pragma unroll
            for (int b = 0; b < Bb; b++) {
                float s = ss[b][cp];
                kk[b] = fmaf(a,  s, kk[b]);
                vv[b] = fmaf(bm, s, vv[b]);
            }
        }
    }

    for (int b = 0; b < Bb; b++) {
        float r  = g_rstd[b*Cc + c];
        float mu = g_mean[b*Cc + c];
        bool masked = false;
        if (!pad && t > 0) masked = (sty_mask[b*Tt + (t-1)] == 0.0f);
        float kk2 = (pad || masked) ? 0.f : kk[b] * r;

        red[c] = mu * kk2;
        __syncthreads();
        for (int st = 128; st > 0; st >>= 1) {
            if (c < st) red[c] += red[c+st];
            __syncthreads();
        }
        if (c == 0) {
            float bias = pad ? -1e30f : (masked ? -10000.0f : -red[0]);
            g_bias[b*TP + t] = bias;
        }
        g_kk2T[((size_t)b*Cc + c)*TP + t] = kk2;
        g_vv  [((size_t)b*TP + t)*Cc + c] = pad ? 0.f : vv[b];
        __syncthreads();
    }
}

// ================= Kernel 4: fused attention main kernel =================
// Grid: (Hh=80, Bb=16). Block: 256 threads. 256 pixels (one full W row) per CTA.
// Thread map: ty = tid&15 (t-group: t in [ty*9, ty*9+9) ; e = j*16+ty),
//             tx = tid>>4 (16 px: [tx*16, tx*16+16)).
// Dynamic smem layout (floats):
//   attn [TP][ASTR]                      : 144*258 = 37152
//   stage (union)                        : 4608   (GEMM1: xs[8][256]+ksd[8][288]; GEMM2: vvd[16][256])
//   biasv[144], xm[256]                  : 400
#define SM_STAGE_OFF  (TP*ASTR)
#define SM_BIAS_OFF   (SM_STAGE_OFF + 4608)
#define SM_XM_OFF     (SM_BIAS_OFF + 144)
#define SM_FLOATS     (SM_XM_OFF + 256)

__global__ void __launch_bounds__(256, 1)
k_main(const float* __restrict__ x, const float* __restrict__ xmask,
       float* __restrict__ y) {
    extern __shared__ float smem[];
    float* attn  = smem;
    float* stage = smem + SM_STAGE_OFF;
    float* ksd   = stage + 2048;
    float* biasv = smem + SM_BIAS_OFF;
    float* xm    = smem + SM_XM_OFF;

    const int tile = blockIdx.x;      // h row
    const int b    = blockIdx.y;
    const int tid  = threadIdx.x;
    const int ty   = tid & 15;
    const int tx   = tid >> 4;
    const int p0   = tile * 256;

    // preload bias + x_mask row
    if (tid < TP) biasv[tid] = g_bias[b*TP + tid];
    xm[tid] = xmask[b*Ww_ + tid];
    __syncthreads();

    // -------- GEMM1: logits[px][t] = sum_c x[c][px]*kk2[c][t] + bias[t] --------
    unsigned long long acc[8][9];
    #pragma unroll
    for (int j = 0; j < 9; j++) {
        float bv = biasv[ty*9 + j];
        unsigned long long bp = pk2(bv, bv);
        #pragma unroll
        for (int i = 0; i < 8; i++) acc[i][j] = bp;
    }

    const float* xb = x + (size_t)b * Cc * HW_ + p0;
    const float* kb = g_kk2T + (size_t)b * Cc * TP;

    for (int c0 = 0; c0 < Cc; c0 += 8) {
        __syncthreads();
        // stage x: 8 rows x 256 px
        for (int i = tid; i < 512; i += 256) {
            int cc = i >> 6, pq = i & 63;
            ((float4*)stage)[i] = *(const float4*)(xb + (size_t)(c0+cc)*HW_ + (pq<<2));
        }
        // stage kk2 rows, duplicated pairs for f32x2
        if (tid < TP) {
            #pragma unroll
            for (int cc = 0; cc < 8; cc++) {
                float v = kb[(size_t)(c0+cc)*TP + tid];
                *(float2*)&ksd[cc*288 + 2*tid] = make_float2(v, v);
            }
        }
        __syncthreads();

        #pragma unroll
        for (int cc = 0; cc < 8; cc++) {
            const float* xr = stage + cc*256 + tx*16;
            unsigned long long xv[8];
            #pragma unroll
            for (int i = 0; i < 8; i++)
                xv[i] = *(const unsigned long long*)(xr + 2*i);
            const float* kr = ksd + cc*288 + 2*(ty*9);
            #pragma unroll
            for (int j = 0; j < 9; j++) {
                unsigned long long kv = *(const unsigned long long*)(kr + 2*j);
                #pragma unroll
                for (int i = 0; i < 8; i++) FFMA2(acc[i][j], xv[i], kv);
            }
        }
    }

    // -------- softmax over t (144), cross-thread via shfl within 16-lane groups --------
    float mx[16];
    #pragma unroll
    for (int i = 0; i < 16; i++) mx[i] = -3.4e38f;
    #pragma unroll
    for (int i = 0; i < 8; i++)
        #pragma unroll
        for (int j = 0; j < 9; j++) {
            float2 v = upk2(acc[i][j]);
            mx[2*i]   = fmaxf(mx[2*i],   v.x);
            mx[2*i+1] = fmaxf(mx[2*i+1], v.y);
        }
    #pragma unroll
    for (int s = 1; s < 16; s <<= 1)
        #pragma unroll
        for (int i = 0; i < 16; i++)
            mx[i] = fmaxf(mx[i], __shfl_xor_sync(0xffffffffu, mx[i], s));

    float sm[16];
    #pragma unroll
    for (int i = 0; i < 16; i++) sm[i] = 0.f;
    #pragma unroll
    for (int j = 0; j < 9; j++) {
        float* arow = attn + (ty*9 + j)*ASTR + tx*16;
        #pragma unroll
        for (int i = 0; i < 8; i++) {
            float2 v = upk2(acc[i][j]);
            float e0 = __expf(v.x - mx[2*i]);
            float e1 = __expf(v.y - mx[2*i+1]);
            sm[2*i]   += e0;
            sm[2*i+1] += e1;
            *(float2*)(arow + 2*i) = make_float2(e0, e1);
        }
    }
    #pragma unroll
    for (int s = 1; s < 16; s <<= 1)
        #pragma unroll
        for (int i = 0; i < 16; i++)
            sm[i] += __shfl_xor_sync(0xffffffffu, sm[i], s);

    unsigned long long rsp[8];
    #pragma unroll
    for (int i = 0; i < 8; i++)
        rsp[i] = pk2(1.0f / sm[2*i], 1.0f / sm[2*i+1]);

    // -------- GEMM2 + epilogue: out[px][e] = (sum_t p*vv) * rsum; y = (x+out)*mask --------
    const float* vvb = g_vv + (size_t)b * TP * Cc;
    const size_t rowb = (size_t)b * Cc;

    for (int h = 0; h < 2; h++) {
        unsigned long long a2[8][8];
        #pragma unroll
        for (int i = 0; i < 8; i++)
            #pragma unroll
            for (int j = 0; j < 8; j++) a2[i][j] = 0ULL;

        for (int tc = 0; tc < 9; tc++) {
            __syncthreads();
            // stage vvd[16][256]: vv rows tc*16..+15, e' = 0..127 of this half, duplicated
            for (int i = tid; i < 2048; i += 256) {
                int tt = i >> 7, ep = i & 127;
                float v = vvb[(size_t)(tc*16 + tt)*Cc + h*128 + ep];
                *(float2*)&stage[tt*256 + 2*ep] = make_float2(v, v);
            }
            __syncthreads();

            #pragma unroll 4
            for (int tt = 0; tt < 16; tt++) {
                const float* arow = attn + (tc*16 + tt)*ASTR + tx*16;
                unsigned long long ap[8];
                #pragma unroll
                for (int i = 0; i < 8; i++)
                    ap[i] = *(const unsigned long long*)(arow + 2*i);
                const float* vr = stage + tt*256 + 2*ty;
                #pragma unroll
                for (int j = 0; j < 8; j++) {
                    unsigned long long vp = *(const unsigned long long*)(vr + j*32);
                    #pragma unroll
                    for (int i = 0; i < 8; i++) FFMA2(a2[i][j], ap[i], vp);
                }
            }
        }

        // epilogue for this half: e = (h*8 + j)*16 + ty
        #pragma unroll
        for (int j = 0; j < 8; j++) {
            int e = (h*8 + j)*16 + ty;
            const float* xr = x + (rowb + e)*HW_ + p0 + tx*16;
            float*       yr = y + (rowb + e)*HW_ + p0 + tx*16;
            #pragma unroll
            for (int q = 0; q < 4; q++) {
                float2 o0 = upk2(mul2(a2[2*q  ][j], rsp[2*q  ]));
                float2 o1 = upk2(mul2(a2[2*q+1][j], rsp[2*q+1]));
                float4 xv = *(const float4*)(xr + 4*q);
                float4 m4 = *(const float4*)&xm[tx*16 + 4*q];
                float4 r;
                r.x = (xv.x + o0.x) * m4.x;
                r.y = (xv.y + o0.y) * m4.y;
                r.z = (xv.z + o1.x) * m4.z;
                r.w = (xv.w + o1.y) * m4.w;
                *(float4*)(yr + 4*q) = r;
            }
        }
    }
}

// ================= launch =================
extern "C" void kernel_launch(void* const* d_in, const int* in_sizes, int n_in,
                              void* d_out, int out_size) {
    const float* x        = (const float*)d_in[0];
    const float* x_mask   = (const float*)d_in[1];
    const float* sty      = (const float*)d_in[2];
    const float* sty_mask = (const float*)d_in[3];
    const float* timev    = (const float*)d_in[4];
    const float* Wq       = (const float*)d_in[5];
    const float* Wk       = (const float*)d_in[6];
    const float* Wv       = (const float*)d_in[7];
    const float* Wl       = (const float*)d_in[8];
    float* y = (float*)d_out;

    // stats (independent of prep kernels)
    k_stats<<<Bb*Cc, 256>>>(x);

    // folded weight matrices
    dim3 pb(16, 16), pg(16, 16);
    k_prepAT <<<pg, pb>>>(Wq, Wk);
    k_prepBmT<<<pg, pb>>>(Wl, Wv);

    // style projections (depends on stats + prep; stream-ordered)
    k_styproj<<<TP, 256>>>(sty, timev, sty_mask);

    // main fused kernel
    int smem_bytes = SM_FLOATS * (int)sizeof(float);
    cudaFuncSetAttribute(k_main, cudaFuncAttributeMaxDynamicSharedMemorySize, smem_bytes);
    dim3 grid(Hh, Bb);
    k_main<<<grid, 256, smem_bytes>>>(x, x_mask, y);
}

// round 10
// speedup vs baseline: 1.0006x; 1.0001x over previous
#include <cuda_runtime.h>
#include <cstdint>

// Problem constants (fixed shapes from setup_inputs)
#define Bb   16
#define Cc   256
#define Hh   80
#define Ww_  256
#define HW_  20480      // Hh*Ww_
#define Tt   128
#define T1   129        // T + time token
#define TP   144        // padded T (16*9)
#define ASTR 258        // attn smem row stride (floats)

// ---------------- static device scratch (no allocation) ----------------
__device__ float g_mean[Bb*Cc];
__device__ float g_rstd[Bb*Cc];
__device__ float g_AT [Cc*Cc];                 // AT[cp][c] = (WqT Wk /16)[c][cp]
__device__ float g_BmT[Cc*Cc];                 // BmT[c][e] = (Wl Wv)[e][c]
__device__ float g_kk2T[(size_t)Bb*Cc*TP];     // [b][c][t]
__device__ float g_vv  [(size_t)Bb*TP*Cc];     // [b][t][e]
__device__ float g_bias[Bb*TP];

// ---------------- f32x2 helpers ----------------
__device__ __forceinline__ unsigned long long pk2(float lo, float hi) {
    unsigned long long r;
    asm("mov.b64 %0, {%1,%2};" : "=l"(r) : "f"(lo), "f"(hi));
    return r;
}
__device__ __forceinline__ float2 upk2(unsigned long long v) {
    float2 r;
    asm("mov.b64 {%0,%1}, %2;" : "=f"(r.x), "=f"(r.y) : "l"(v));
    return r;
}
#define FFMA2(d, a, b) asm("fma.rn.f32x2 %0, %1, %2, %0;" : "+l"(d) : "l"(a), "l"(b))
__device__ __forceinline__ unsigned long long mul2(unsigned long long a, unsigned long long b) {
    unsigned long long d;
    asm("mul.rn.f32x2 %0, %1, %2;" : "=l"(d) : "l"(a), "l"(b));
    return d;
}

// ================= Kernel 1: per-(b,c) instance-norm stats =================
__global__ void k_stats(const float* __restrict__ x) {
    int bc = blockIdx.x;                 // b*Cc + c
    int tid = threadIdx.x;
    const float4* xp = (const float4*)(x + (size_t)bc * HW_);
    float s = 0.f, s2 = 0.f;
    for (int i = tid; i < HW_/4; i += 256) {
        float4 v = xp[i];
        s  += v.x + v.y + v.z + v.w;
        s2 += v.x*v.x + v.y*v.y + v.z*v.z + v.w*v.w;
    }
    __shared__ float rs[256], rq[256];
    rs[tid] = s; rq[tid] = s2;
    __syncthreads();
    for (int st = 128; st > 0; st >>= 1) {
        if (tid < st) { rs[tid] += rs[tid+st]; rq[tid] += rq[tid+st]; }
        __syncthreads();
    }
    if (tid == 0) {
        float mean = rs[0] * (1.0f / HW_);
        float var  = rq[0] * (1.0f / HW_) - mean * mean;
        g_mean[bc] = mean;
        g_rstd[bc] = rsqrtf(var + 1e-5f);
    }
}

// ================= Kernel 2a: AT[i][j] = (1/16) * sum_d Wk[d][i]*Wq[d][j] =================
__global__ void k_prepAT(const float* __restrict__ Wq, const float* __restrict__ Wk) {
    __shared__ float As[16][17], Bs[16][17];
    int i0 = blockIdx.y * 16, j0 = blockIdx.x * 16;
    int ty = threadIdx.y, tx = threadIdx.x;
    float acc = 0.f;
    for (int kt = 0; kt < Cc; kt += 16) {
        As[ty][tx] = Wk[(kt+ty)*Cc + i0 + tx];
        Bs[ty][tx] = Wq[(kt+ty)*Cc + j0 + tx];
        __syncthreads();
        #pragma unroll
        for (int kk = 0; kk < 16; kk++) acc += As[kk][ty] * Bs[kk][tx];
        __syncthreads();
    }
    g_AT[(i0+ty)*Cc + j0 + tx] = acc * 0.0625f;
}

// ================= Kernel 2b: BmT[c][e] = sum_d Wv[d][c]*Wl[e][d] =================
__global__ void k_prepBmT(const float* __restrict__ Wl, const float* __restrict__ Wv) {
    __shared__ float Vs[16][17], Ls[16][17];
    int c0 = blockIdx.y * 16, e0 = blockIdx.x * 16;
    int ty = threadIdx.y, tx = threadIdx.x;
    float acc = 0.f;
    for (int dt = 0; dt < Cc; dt += 16) {
        Vs[ty][tx] = Wv[(dt+ty)*Cc + c0 + tx];
        Ls[ty][tx] = Wl[(e0+ty)*Cc + dt + tx];   // Ls[e_local][d_local]
        __syncthreads();
        #pragma unroll
        for (int dd = 0; dd < 16; dd++) acc += Vs[dd][ty] * Ls[tx][dd];
        __syncthreads();
    }
    g_BmT[(c0+ty)*Cc + e0 + tx] = acc;
}

// ================= Kernel 3: style projections kk2T / vv / bias =================
// One block per t (144 blocks), loops all 16 batches, 256 threads (=c or e).
__global__ void k_styproj(const float* __restrict__ sty,
                          const float* __restrict__ timev,
                          const float* __restrict__ sty_mask) {
    int t = blockIdx.x;          // 0..TP-1
    int c = threadIdx.x;         // 0..255
    bool pad = (t >= T1);
    __shared__ float ss[Bb][Cc];
    __shared__ float red[256];

    if (!pad) {
        for (int b = 0; b < Bb; b++)
            ss[b][c] = (t == 0) ? timev[b*Cc + c]
                                : sty[((size_t)b*Cc + c)*Tt + (t-1)];
    }
    __syncthreads();

    float kk[Bb], vv[Bb];
    #pragma unroll
    for (int b = 0; b < Bb; b++) { kk[b] = 0.f; vv[b] = 0.f; }

    if (!pad) {
        for (int cp = 0; cp < Cc; cp++) {
            float a  = g_AT [cp*Cc + c];
            float bm = g_BmT[cp*Cc + c];
            #pragma unroll
            for (int b = 0; b < Bb; b++) {
                float s = ss[b][cp];
                kk[b] = fmaf(a,  s, kk[b]);
                vv[b] = fmaf(bm, s, vv[b]);
            }
        }
    }

    for (int b = 0; b < Bb; b++) {
        float r  = g_rstd[b*Cc + c];
        float mu = g_mean[b*Cc + c];
        bool masked = false;
        if (!pad && t > 0) masked = (sty_mask[b*Tt + (t-1)] == 0.0f);
        float kk2 = (pad || masked) ? 0.f : kk[b] * r;

        red[c] = mu * kk2;
        __syncthreads();
        for (int st = 128; st > 0; st >>= 1) {
            if (c < st) red[c] += red[c+st];
            __syncthreads();
        }
        if (c == 0) {
            float bias = pad ? -1e30f : (masked ? -10000.0f : -red[0]);
            g_bias[b*TP + t] = bias;
        }
        g_kk2T[((size_t)b*Cc + c)*TP + t] = kk2;
        g_vv  [((size_t)b*TP + t)*Cc + c] = pad ? 0.f : vv[b];
        __syncthreads();
    }
}

// ================= Kernel 4: fused attention main kernel =================
// Grid: (Hh=80, Bb=16). Block: 256 threads. 256 pixels (one full W row) per CTA.
// Thread map: ty = tid&15 (t-group: t in [ty*9, ty*9+9) ; e = j*16+ty),
//             tx = tid>>4 (16 px: [tx*16, tx*16+16)).
// Dynamic smem layout (floats):
//   attn [TP][ASTR]                      : 144*258 = 37152
//   stage (union)                        : 4608   (GEMM1: xs[8][256]+ksd[8][288]; GEMM2: vvd[16][256])
//   biasv[144], xm[256]                  : 400
#define SM_STAGE_OFF  (TP*ASTR)
#define SM_BIAS_OFF   (SM_STAGE_OFF + 4608)
#define SM_XM_OFF     (SM_BIAS_OFF + 144)
#define SM_FLOATS     (SM_XM_OFF + 256)

__global__ void __launch_bounds__(256, 1)
k_main(const float* __restrict__ x, const float* __restrict__ xmask,
       float* __restrict__ y) {
    extern __shared__ float smem[];
    float* attn  = smem;
    float* stage = smem + SM_STAGE_OFF;
    float* ksd   = stage + 2048;
    float* biasv = smem + SM_BIAS_OFF;
    float* xm    = smem + SM_XM_OFF;

    const int tile = blockIdx.x;      // h row
    const int b    = blockIdx.y;
    const int tid  = threadIdx.x;
    const int ty   = tid & 15;
    const int tx   = tid >> 4;
    const int p0   = tile * 256;

    // preload bias + x_mask row
    if (tid < TP) biasv[tid] = g_bias[b*TP + tid];
    xm[tid] = xmask[b*Ww_ + tid];
    __syncthreads();

    // -------- GEMM1: logits[px][t] = sum_c x[c][px]*kk2[c][t] + bias[t] --------
    unsigned long long acc[8][9];
    #pragma unroll
    for (int j = 0; j < 9; j++) {
        float bv = biasv[ty*9 + j];
        unsigned long long bp = pk2(bv, bv);
        #pragma unroll
        for (int i = 0; i < 8; i++) acc[i][j] = bp;
    }

    const float* xb = x + (size_t)b * Cc * HW_ + p0;
    const float* kb = g_kk2T + (size_t)b * Cc * TP;

    for (int c0 = 0; c0 < Cc; c0 += 8) {
        __syncthreads();
        // stage x: 8 rows x 256 px
        for (int i = tid; i < 512; i += 256) {
            int cc = i >> 6, pq = i & 63;
            ((float4*)stage)[i] = *(const float4*)(xb + (size_t)(c0+cc)*HW_ + (pq<<2));
        }
        // stage kk2 rows, duplicated pairs for f32x2
        if (tid < TP) {
            #pragma unroll
            for (int cc = 0; cc < 8; cc++) {
                float v = kb[(size_t)(c0+cc)*TP + tid];
                *(float2*)&ksd[cc*288 + 2*tid] = make_float2(v, v);
            }
        }
        __syncthreads();

        #pragma unroll
        for (int cc = 0; cc < 8; cc++) {
            const float* xr = stage + cc*256 + tx*16;
            unsigned long long xv[8];
            #pragma unroll
            for (int i = 0; i < 8; i++)
                xv[i] = *(const unsigned long long*)(xr + 2*i);
            const float* kr = ksd + cc*288 + 2*(ty*9);
            #pragma unroll
            for (int j = 0; j < 9; j++) {
                unsigned long long kv = *(const unsigned long long*)(kr + 2*j);
                #pragma unroll
                for (int i = 0; i < 8; i++) FFMA2(acc[i][j], xv[i], kv);
            }
        }
    }

    // -------- softmax over t (144), cross-thread via shfl within 16-lane groups --------
    float mx[16];
    #pragma unroll
    for (int i = 0; i < 16; i++) mx[i] = -3.4e38f;
    #pragma unroll
    for (int i = 0; i < 8; i++)
        #pragma unroll
        for (int j = 0; j < 9; j++) {
            float2 v = upk2(acc[i][j]);
            mx[2*i]   = fmaxf(mx[2*i],   v.x);
            mx[2*i+1] = fmaxf(mx[2*i+1], v.y);
        }
    #pragma unroll
    for (int s = 1; s < 16; s <<= 1)
        #pragma unroll
        for (int i = 0; i < 16; i++)
            mx[i] = fmaxf(mx[i], __shfl_xor_sync(0xffffffffu, mx[i], s));

    float sm[16];
    #pragma unroll
    for (int i = 0; i < 16; i++) sm[i] = 0.f;
    #pragma unroll
    for (int j = 0; j < 9; j++) {
        float* arow = attn + (ty*9 + j)*ASTR + tx*16;
        #pragma unroll
        for (int i = 0; i < 8; i++) {
            float2 v = upk2(acc[i][j]);
            float e0 = __expf(v.x - mx[2*i]);
            float e1 = __expf(v.y - mx[2*i+1]);
            sm[2*i]   += e0;
            sm[2*i+1] += e1;
            *(float2*)(arow + 2*i) = make_float2(e0, e1);
        }
    }
    #pragma unroll
    for (int s = 1; s < 16; s <<= 1)
        #pragma unroll
        for (int i = 0; i < 16; i++)
            sm[i] += __shfl_xor_sync(0xffffffffu, sm[i], s);

    unsigned long long rsp[8];
    #pragma unroll
    for (int i = 0; i < 8; i++)
        rsp[i] = pk2(1.0f / sm[2*i], 1.0f / sm[2*i+1]);

    // -------- GEMM2 + epilogue: out[px][e] = (sum_t p*vv) * rsum; y = (x+out)*mask --------
    const float* vvb = g_vv + (size_t)b * TP * Cc;
    const size_t rowb = (size_t)b * Cc;

    for (int h = 0; h < 2; h++) {
        unsigned long long a2[8][8];
        #pragma unroll
        for (int i = 0; i < 8; i++)
            #pragma unroll
            for (int j = 0; j < 8; j++) a2[i][j] = 0ULL;

        for (int tc = 0; tc < 9; tc++) {
            __syncthreads();
            // stage vvd[16][256]: vv rows tc*16..+15, e' = 0..127 of this half, duplicated
            for (int i = tid; i < 2048; i += 256) {
                int tt = i >> 7, ep = i & 127;
                float v = vvb[(size_t)(tc*16 + tt)*Cc + h*128 + ep];
                *(float2*)&stage[tt*256 + 2*ep] = make_float2(v, v);
            }
            __syncthreads();

            #pragma unroll 4
            for (int tt = 0; tt < 16; tt++) {
                const float* arow = attn + (tc*16 + tt)*ASTR + tx*16;
                unsigned long long ap[8];
                #pragma unroll
                for (int i = 0; i < 8; i++)
                    ap[i] = *(const unsigned long long*)(arow + 2*i);
                const float* vr = stage + tt*256 + 2*ty;
                #pragma unroll
                for (int j = 0; j < 8; j++) {
                    unsigned long long vp = *(const unsigned long long*)(vr + j*32);
                    #pragma unroll
                    for (int i = 0; i < 8; i++) FFMA2(a2[i][j], ap[i], vp);
                }
            }
        }

        // epilogue for this half: e = (h*8 + j)*16 + ty
        #pragma unroll
        for (int j = 0; j < 8; j++) {
            int e = (h*8 + j)*16 + ty;
            const float* xr = x + (rowb + e)*HW_ + p0 + tx*16;
            float*       yr = y + (rowb + e)*HW_ + p0 + tx*16;
            #pragma unroll
            for (int q = 0; q < 4; q++) {
                float2 o0 = upk2(mul2(a2[2*q  ][j], rsp[2*q  ]));
                float2 o1 = upk2(mul2(a2[2*q+1][j], rsp[2*q+1]));
                float4 xv = *(const float4*)(xr + 4*q);
                float4 m4 = *(const float4*)&xm[tx*16 + 4*q];
                float4 r;
                r.x = (xv.x + o0.x) * m4.x;
                r.y = (xv.y + o0.y) * m4.y;
                r.z = (xv.z + o1.x) * m4.z;
                r.w = (xv.w + o1.y) * m4.w;
                *(float4*)(yr + 4*q) = r;
            }
        }
    }
}

// ================= launch =================
extern "C" void kernel_launch(void* const* d_in, const int* in_sizes, int n_in,
                              void* d_out, int out_size) {
    const float* x        = (const float*)d_in[0];
    const float* x_mask   = (const float*)d_in[1];
    const float* sty      = (const float*)d_in[2];
    const float* sty_mask = (const float*)d_in[3];
    const float* timev    = (const float*)d_in[4];
    const float* Wq       = (const float*)d_in[5];
    const float* Wk       = (const float*)d_in[6];
    const float* Wv       = (const float*)d_in[7];
    const float* Wl       = (const float*)d_in[8];
    float* y = (float*)d_out;

    // stats (independent of prep kernels)
    k_stats<<<Bb*Cc, 256>>>(x);

    // folded weight matrices
    dim3 pb(16, 16), pg(16, 16);
    k_prepAT <<<pg, pb>>>(Wq, Wk);
    k_prepBmT<<<pg, pb>>>(Wl, Wv);

    // style projections (depends on stats + prep; stream-ordered)
    k_styproj<<<TP, 256>>>(sty, timev, sty_mask);

    // main fused kernel
    int smem_bytes = SM_FLOATS * (int)sizeof(float);
    cudaFuncSetAttribute(k_main, cudaFuncAttributeMaxDynamicSharedMemorySize, smem_bytes);
    dim3 grid(Hh, Bb);
    k_main<<<grid, 256, smem_bytes>>>(x, x_mask, y);
}

// round 11
// speedup vs baseline: 1.0011x; 1.0005x over previous
#include <cuda_runtime.h>
#include <cstdint>

// Problem constants (fixed shapes from setup_inputs)
#define Bb   16
#define Cc   256
#define Hh   80
#define Ww_  256
#define HW_  20480      // Hh*Ww_
#define Tt   128
#define T1   129        // T + time token
#define TP   144        // padded T (16*9)
#define ASTR 258        // attn smem row stride (floats)

// ---------------- static device scratch (no allocation) ----------------
__device__ float g_mean[Bb*Cc];
__device__ float g_rstd[Bb*Cc];
__device__ float g_AT [Cc*Cc];                 // AT[cp][c] = (WqT Wk /16)[c][cp]
__device__ float g_BmT[Cc*Cc];                 // BmT[c][e] = (Wl Wv)[e][c]
__device__ float g_kk2T[(size_t)Bb*Cc*TP];     // [b][c][t]
__device__ float g_vv  [(size_t)Bb*TP*Cc];     // [b][t][e]
__device__ float g_bias[Bb*TP];

// ---------------- f32x2 helpers ----------------
__device__ __forceinline__ unsigned long long pk2(float lo, float hi) {
    unsigned long long r;
    asm("mov.b64 %0, {%1,%2};" : "=l"(r) : "f"(lo), "f"(hi));
    return r;
}
__device__ __forceinline__ float2 upk2(unsigned long long v) {
    float2 r;
    asm("mov.b64 {%0,%1}, %2;" : "=f"(r.x), "=f"(r.y) : "l"(v));
    return r;
}
#define FFMA2(d, a, b) asm("fma.rn.f32x2 %0, %1, %2, %0;" : "+l"(d) : "l"(a), "l"(b))
__device__ __forceinline__ unsigned long long mul2(unsigned long long a, unsigned long long b) {
    unsigned long long d;
    asm("mul.rn.f32x2 %0, %1, %2;" : "=l"(d) : "l"(a), "l"(b));
    return d;
}

// ================= Kernel 1: per-(b,c) instance-norm stats =================
__global__ void k_stats(const float* __restrict__ x) {
    int bc = blockIdx.x;                 // b*Cc + c
    int tid = threadIdx.x;
    const float4* xp = (const float4*)(x + (size_t)bc * HW_);
    float s = 0.f, s2 = 0.f;
    for (int i = tid; i < HW_/4; i += 256) {
        float4 v = xp[i];
        s  += v.x + v.y + v.z + v.w;
        s2 += v.x*v.x + v.y*v.y + v.z*v.z + v.w*v.w;
    }
    __shared__ float rs[256], rq[256];
    rs[tid] = s; rq[tid] = s2;
    __syncthreads();
    for (int st = 128; st > 0; st >>= 1) {
        if (tid < st) { rs[tid] += rs[tid+st]; rq[tid] += rq[tid+st]; }
        __syncthreads();
    }
    if (tid == 0) {
        float mean = rs[0] * (1.0f / HW_);
        float var  = rq[0] * (1.0f / HW_) - mean * mean;
        g_mean[bc] = mean;
        g_rstd[bc] = rsqrtf(var + 1e-5f);
    }
}

// ================= Kernel 2a: AT[i][j] = (1/16) * sum_d Wk[d][i]*Wq[d][j] =================
__global__ void k_prepAT(const float* __restrict__ Wq, const float* __restrict__ Wk) {
    __shared__ float As[16][17], Bs[16][17];
    int i0 = blockIdx.y * 16, j0 = blockIdx.x * 16;
    int ty = threadIdx.y, tx = threadIdx.x;
    float acc = 0.f;
    for (int kt = 0; kt < Cc; kt += 16) {
        As[ty][tx] = Wk[(kt+ty)*Cc + i0 + tx];
        Bs[ty][tx] = Wq[(kt+ty)*Cc + j0 + tx];
        __syncthreads();
        #pragma unroll
        for (int kk = 0; kk < 16; kk++) acc += As[kk][ty] * Bs[kk][tx];
        __syncthreads();
    }
    g_AT[(i0+ty)*Cc + j0 + tx] = acc * 0.0625f;
}

// ================= Kernel 2b: BmT[c][e] = sum_d Wv[d][c]*Wl[e][d] =================
__global__ void k_prepBmT(const float* __restrict__ Wl, const float* __restrict__ Wv) {
    __shared__ float Vs[16][17], Ls[16][17];
    int c0 = blockIdx.y * 16, e0 = blockIdx.x * 16;
    int ty = threadIdx.y, tx = threadIdx.x;
    float acc = 0.f;
    for (int dt = 0; dt < Cc; dt += 16) {
        Vs[ty][tx] = Wv[(dt+ty)*Cc + c0 + tx];
        Ls[ty][tx] = Wl[(e0+ty)*Cc + dt + tx];   // Ls[e_local][d_local]
        __syncthreads();
        #pragma unroll
        for (int dd = 0; dd < 16; dd++) acc += Vs[dd][ty] * Ls[tx][dd];
        __syncthreads();
    }
    g_BmT[(c0+ty)*Cc + e0 + tx] = acc;
}

// ================= Kernel 3: style projections kk2T / vv / bias =================
// One block per t (144 blocks), loops all 16 batches, 256 threads (=c or e).
__global__ void k_styproj(const float* __restrict__ sty,
                          const float* __restrict__ timev,
                          const float* __restrict__ sty_mask) {
    int t = blockIdx.x;          // 0..TP-1
    int c = threadIdx.x;         // 0..255
    bool pad = (t >= T1);
    __shared__ float ss[Bb][Cc];
    __shared__ float red[256];

    if (!pad) {
        for (int b = 0; b < Bb; b++)
            ss[b][c] = (t == 0) ? timev[b*Cc + c]
                                : sty[((size_t)b*Cc + c)*Tt + (t-1)];
    }
    __syncthreads();

    float kk[Bb], vv[Bb];
    #pragma unroll
    for (int b = 0; b < Bb; b++) { kk[b] = 0.f; vv[b] = 0.f; }

    if (!pad) {
        for (int cp = 0; cp < Cc; cp++) {
            float a  = g_AT [cp*Cc + c];
            float bm = g_BmT[cp*Cc + c];
            #pragma unroll
            for (int b = 0; b < Bb; b++) {
                float s = ss[b][cp];
                kk[b] = fmaf(a,  s, kk[b]);
                vv[b] = fmaf(bm, s, vv[b]);
            }
        }
    }

    for (int b = 0; b < Bb; b++) {
        float r  = g_rstd[b*Cc + c];
        float mu = g_mean[b*Cc + c];
        bool masked = false;
        if (!pad && t > 0) masked = (sty_mask[b*Tt + (t-1)] == 0.0f);
        float kk2 = (pad || masked) ? 0.f : kk[b] * r;

        red[c] = mu * kk2;
        __syncthreads();
        for (int st = 128; st > 0; st >>= 1) {
            if (c < st) red[c] += red[c+st];
            __syncthreads();
        }
        if (c == 0) {
            float bias = pad ? -1e30f : (masked ? -10000.0f : -red[0]);
            g_bias[b*TP + t] = bias;
        }
        g_kk2T[((size_t)b*Cc + c)*TP + t] = kk2;
        g_vv  [((size_t)b*TP + t)*Cc + c] = pad ? 0.f : vv[b];
        __syncthreads();
    }
}

// ================= Kernel 4: fused attention main kernel =================
// Grid: (Hh=80, Bb=16). Block: 256 threads. 256 pixels (one full W row) per CTA.
// Thread map: ty = tid&15 (t-group: t in [ty*9, ty*9+9) ; e = j*16+ty),
//             tx = tid>>4 (16 px: [tx*16, tx*16+16)).
// Dynamic smem layout (floats):
//   attn [TP][ASTR]                      : 144*258 = 37152
//   stage (union)                        : 4608   (GEMM1: xs[8][256]+ksd[8][288]; GEMM2: vvd[16][256])
//   biasv[144], xm[256]                  : 400
#define SM_STAGE_OFF  (TP*ASTR)
#define SM_BIAS_OFF   (SM_STAGE_OFF + 4608)
#define SM_XM_OFF     (SM_BIAS_OFF + 144)
#define SM_FLOATS     (SM_XM_OFF + 256)

__global__ void __launch_bounds__(256, 1)
k_main(const float* __restrict__ x, const float* __restrict__ xmask,
       float* __restrict__ y) {
    extern __shared__ float smem[];
    float* attn  = smem;
    float* stage = smem + SM_STAGE_OFF;
    float* ksd   = stage + 2048;
    float* biasv = smem + SM_BIAS_OFF;
    float* xm    = smem + SM_XM_OFF;

    const int tile = blockIdx.x;      // h row
    const int b    = blockIdx.y;
    const int tid  = threadIdx.x;
    const int ty   = tid & 15;
    const int tx   = tid >> 4;
    const int p0   = tile * 256;

    // preload bias + x_mask row
    if (tid < TP) biasv[tid] = g_bias[b*TP + tid];
    xm[tid] = xmask[b*Ww_ + tid];
    __syncthreads();

    // -------- GEMM1: logits[px][t] = sum_c x[c][px]*kk2[c][t] + bias[t] --------
    unsigned long long acc[8][9];
    #pragma unroll
    for (int j = 0; j < 9; j++) {
        float bv = biasv[ty*9 + j];
        unsigned long long bp = pk2(bv, bv);
        #pragma unroll
        for (int i = 0; i < 8; i++) acc[i][j] = bp;
    }

    const float* xb = x + (size_t)b * Cc * HW_ + p0;
    const float* kb = g_kk2T + (size_t)b * Cc * TP;

    for (int c0 = 0; c0 < Cc; c0 += 8) {
        __syncthreads();
        // stage x: 8 rows x 256 px
        for (int i = tid; i < 512; i += 256) {
            int cc = i >> 6, pq = i & 63;
            ((float4*)stage)[i] = *(const float4*)(xb + (size_t)(c0+cc)*HW_ + (pq<<2));
        }
        // stage kk2 rows, duplicated pairs for f32x2
        if (tid < TP) {
            #pragma unroll
            for (int cc = 0; cc < 8; cc++) {
                float v = kb[(size_t)(c0+cc)*TP + tid];
                *(float2*)&ksd[cc*288 + 2*tid] = make_float2(v, v);
            }
        }
        __syncthreads();

        #pragma unroll
        for (int cc = 0; cc < 8; cc++) {
            const float* xr = stage + cc*256 + tx*16;
            unsigned long long xv[8];
            #pragma unroll
            for (int i = 0; i < 8; i++)
                xv[i] = *(const unsigned long long*)(xr + 2*i);
            const float* kr = ksd + cc*288 + 2*(ty*9);
            #pragma unroll
            for (int j = 0; j < 9; j++) {
                unsigned long long kv = *(const unsigned long long*)(kr + 2*j);
                #pragma unroll
                for (int i = 0; i < 8; i++) FFMA2(acc[i][j], xv[i], kv);
            }
        }
    }

    // -------- softmax over t (144), cross-thread via shfl within 16-lane groups --------
    float mx[16];
    #pragma unroll
    for (int i = 0; i < 16; i++) mx[i] = -3.4e38f;
    #pragma unroll
    for (int i = 0; i < 8; i++)
        #pragma unroll
        for (int j = 0; j < 9; j++) {
            float2 v = upk2(acc[i][j]);
            mx[2*i]   = fmaxf(mx[2*i],   v.x);
            mx[2*i+1] = fmaxf(mx[2*i+1], v.y);
        }
    #pragma unroll
    for (int s = 1; s < 16; s <<= 1)
        #pragma unroll
        for (int i = 0; i < 16; i++)
            mx[i] = fmaxf(mx[i], __shfl_xor_sync(0xffffffffu, mx[i], s));

    float sm[16];
    #pragma unroll
    for (int i = 0; i < 16; i++) sm[i] = 0.f;
    #pragma unroll
    for (int j = 0; j < 9; j++) {
        float* arow = attn + (ty*9 + j)*ASTR + tx*16;
        #pragma unroll
        for (int i = 0; i < 8; i++) {
            float2 v = upk2(acc[i][j]);
            float e0 = __expf(v.x - mx[2*i]);
            float e1 = __expf(v.y - mx[2*i+1]);
            sm[2*i]   += e0;
            sm[2*i+1] += e1;
            *(float2*)(arow + 2*i) = make_float2(e0, e1);
        }
    }
    #pragma unroll
    for (int s = 1; s < 16; s <<= 1)
        #pragma unroll
        for (int i = 0; i < 16; i++)
            sm[i] += __shfl_xor_sync(0xffffffffu, sm[i], s);

    unsigned long long rsp[8];
    #pragma unroll
    for (int i = 0; i < 8; i++)
        rsp[i] = pk2(1.0f / sm[2*i], 1.0f / sm[2*i+1]);

    // -------- GEMM2 + epilogue: out[px][e] = (sum_t p*vv) * rsum; y = (x+out)*mask --------
    const float* vvb = g_vv + (size_t)b * TP * Cc;
    const size_t rowb = (size_t)b * Cc;

    for (int h = 0; h < 2; h++) {
        unsigned long long a2[8][8];
        #pragma unroll
        for (int i = 0; i < 8; i++)
            #pragma unroll
            for (int j = 0; j < 8; j++) a2[i][j] = 0ULL;

        for (int tc = 0; tc < 9; tc++) {
            __syncthreads();
            // stage vvd[16][256]: vv rows tc*16..+15, e' = 0..127 of this half, duplicated
            for (int i = tid; i < 2048; i += 256) {
                int tt = i >> 7, ep = i & 127;
                float v = vvb[(size_t)(tc*16 + tt)*Cc + h*128 + ep];
                *(float2*)&stage[tt*256 + 2*ep] = make_float2(v, v);
            }
            __syncthreads();

            #pragma unroll 4
            for (int tt = 0; tt < 16; tt++) {
                const float* arow = attn + (tc*16 + tt)*ASTR + tx*16;
                unsigned long long ap[8];
                #pragma unroll
                for (int i = 0; i < 8; i++)
                    ap[i] = *(const unsigned long long*)(arow + 2*i);
                const float* vr = stage + tt*256 + 2*ty;
                #pragma unroll
                for (int j = 0; j < 8; j++) {
                    unsigned long long vp = *(const unsigned long long*)(vr + j*32);
                    #pragma unroll
                    for (int i = 0; i < 8; i++) FFMA2(a2[i][j], ap[i], vp);
                }
            }
        }

        // epilogue for this half: e = (h*8 + j)*16 + ty
        #pragma unroll
        for (int j = 0; j < 8; j++) {
            int e = (h*8 + j)*16 + ty;
            const float* xr = x + (rowb + e)*HW_ + p0 + tx*16;
            float*       yr = y + (rowb + e)*HW_ + p0 + tx*16;
            #pragma unroll
            for (int q = 0; q < 4; q++) {
                float2 o0 = upk2(mul2(a2[2*q  ][j], rsp[2*q  ]));
                float2 o1 = upk2(mul2(a2[2*q+1][j], rsp[2*q+1]));
                float4 xv = *(const float4*)(xr + 4*q);
                float4 m4 = *(const float4*)&xm[tx*16 + 4*q];
                float4 r;
                r.x = (xv.x + o0.x) * m4.x;
                r.y = (xv.y + o0.y) * m4.y;
                r.z = (xv.z + o1.x) * m4.z;
                r.w = (xv.w + o1.y) * m4.w;
                *(float4*)(yr + 4*q) = r;
            }
        }
    }
}

// ================= launch =================
extern "C" void kernel_launch(void* const* d_in, const int* in_sizes, int n_in,
                              void* d_out, int out_size) {
    const float* x        = (const float*)d_in[0];
    const float* x_mask   = (const float*)d_in[1];
    const float* sty      = (const float*)d_in[2];
    const float* sty_mask = (const float*)d_in[3];
    const float* timev    = (const float*)d_in[4];
    const float* Wq       = (const float*)d_in[5];
    const float* Wk       = (const float*)d_in[6];
    const float* Wv       = (const float*)d_in[7];
    const float* Wl       = (const float*)d_in[8];
    float* y = (float*)d_out;

    // stats (independent of prep kernels)
    k_stats<<<Bb*Cc, 256>>>(x);

    // folded weight matrices
    dim3 pb(16, 16), pg(16, 16);
    k_prepAT <<<pg, pb>>>(Wq, Wk);
    k_prepBmT<<<pg, pb>>>(Wl, Wv);

    // style projections (depends on stats + prep; stream-ordered)
    k_styproj<<<TP, 256>>>(sty, timev, sty_mask);

    // main fused kernel
    int smem_bytes = SM_FLOATS * (int)sizeof(float);
    cudaFuncSetAttribute(k_main, cudaFuncAttributeMaxDynamicSharedMemorySize, smem_bytes);
    dim3 grid(Hh, Bb);
    k_main<<<grid, 256, smem_bytes>>>(x, x_mask, y);
}

// round 13
// speedup vs baseline: 1.6135x; 1.6117x over previous
#include <cuda_runtime.h>
#include <cstdint>

// Problem constants (fixed shapes from setup_inputs)
#define Bb   16
#define Cc   256
#define Hh   80
#define Ww_  256
#define HW_  20480      // Hh*Ww_
#define Tt   128
#define T1   129        // T + time token
#define TP   144        // padded T (16*9)
#define PX   128        // pixels per CTA tile
#define ASTR 130        // attn smem row stride (floats) — MUST be even (8B accesses)

// ---------------- static device scratch (no allocation) ----------------
__device__ float g_mean[Bb*Cc];
__device__ float g_rstd[Bb*Cc];
__device__ __align__(16) float g_AT [Cc*Cc];              // AT[cp][c] = (WqT Wk /16)[c][cp]
__device__ __align__(16) float g_BmT[Cc*Cc];              // BmT[cp][e] = (Wl Wv)[e][cp]
__device__ __align__(16) float g_kk2T[(size_t)Bb*Cc*TP];  // [b][c][t]
__device__ __align__(16) float g_vv  [(size_t)Bb*TP*Cc];  // [b][t][e]
__device__ float g_bias[Bb*TP];

// ---------------- f32x2 helpers ----------------
__device__ __forceinline__ unsigned long long pk2(float lo, float hi) {
    unsigned long long r;
    asm("mov.b64 %0, {%1,%2};" : "=l"(r) : "f"(lo), "f"(hi));
    return r;
}
__device__ __forceinline__ float2 upk2(unsigned long long v) {
    float2 r;
    asm("mov.b64 {%0,%1}, %2;" : "=f"(r.x), "=f"(r.y) : "l"(v));
    return r;
}
#define FFMA2(d, a, b) asm("fma.rn.f32x2 %0, %1, %2, %0;" : "+l"(d) : "l"(a), "l"(b))
__device__ __forceinline__ unsigned long long mul2(unsigned long long a, unsigned long long b) {
    unsigned long long d;
    asm("mul.rn.f32x2 %0, %1, %2;" : "=l"(d) : "l"(a), "l"(b));
    return d;
}

// ---------------- cp.async helpers ----------------
__device__ __forceinline__ void cpa16(uint32_t dst, const void* src) {
    asm volatile("cp.async.cg.shared.global [%0], [%1], 16;\n" :: "r"(dst), "l"(src));
}
#define CP_COMMIT() asm volatile("cp.async.commit_group;\n" ::: "memory")
#define CP_WAIT0()  asm volatile("cp.async.wait_group 0;\n" ::: "memory")

// ================= Kernel 1: per-(b,c) instance-norm stats =================
__global__ void k_stats(const float* __restrict__ x) {
    int bc = blockIdx.x;                 // b*Cc + c
    int tid = threadIdx.x;
    const float4* xp = (const float4*)(x + (size_t)bc * HW_);
    float s = 0.f, s2 = 0.f;
    for (int i = tid; i < HW_/4; i += 256) {
        float4 v = xp[i];
        s  += v.x + v.y + v.z + v.w;
        s2 += v.x*v.x + v.y*v.y + v.z*v.z + v.w*v.w;
    }
    __shared__ float rs[256], rq[256];
    rs[tid] = s; rq[tid] = s2;
    __syncthreads();
    for (int st = 128; st > 0; st >>= 1) {
        if (tid < st) { rs[tid] += rs[tid+st]; rq[tid] += rq[tid+st]; }
        __syncthreads();
    }
    if (tid == 0) {
        float mean = rs[0] * (1.0f / HW_);
        float var  = rq[0] * (1.0f / HW_) - mean * mean;
        g_mean[bc] = mean;
        g_rstd[bc] = rsqrtf(var + 1e-5f);
    }
}

// ================= Kernel 2a: AT[i][j] = (1/16) * sum_d Wk[d][i]*Wq[d][j] =================
__global__ void k_prepAT(const float* __restrict__ Wq, const float* __restrict__ Wk) {
    __shared__ float As[16][17], Bs[16][17];
    int i0 = blockIdx.y * 16, j0 = blockIdx.x * 16;
    int ty = threadIdx.y, tx = threadIdx.x;
    float acc = 0.f;
    for (int kt = 0; kt < Cc; kt += 16) {
        As[ty][tx] = Wk[(kt+ty)*Cc + i0 + tx];
        Bs[ty][tx] = Wq[(kt+ty)*Cc + j0 + tx];
        __syncthreads();
        #pragma unroll
        for (int kk = 0; kk < 16; kk++) acc += As[kk][ty] * Bs[kk][tx];
        __syncthreads();
    }
    g_AT[(i0+ty)*Cc + j0 + tx] = acc * 0.0625f;
}

// ================= Kernel 2b: BmT[c][e] = sum_d Wv[d][c]*Wl[e][d] =================
__global__ void k_prepBmT(const float* __restrict__ Wl, const float* __restrict__ Wv) {
    __shared__ float Vs[16][17], Ls[16][17];
    int c0 = blockIdx.y * 16, e0 = blockIdx.x * 16;
    int ty = threadIdx.y, tx = threadIdx.x;
    float acc = 0.f;
    for (int dt = 0; dt < Cc; dt += 16) {
        Vs[ty][tx] = Wv[(dt+ty)*Cc + c0 + tx];
        Ls[ty][tx] = Wl[(e0+ty)*Cc + dt + tx];   // Ls[e_local][d_local]
        __syncthreads();
        #pragma unroll
        for (int dd = 0; dd < 16; dd++) acc += Vs[dd][ty] * Ls[tx][dd];
        __syncthreads();
    }
    g_BmT[(c0+ty)*Cc + e0 + tx] = acc;
}

// ================= Kernel 3: style projections kk2T / vv / bias =================
// grid (TP, 2): y=0 -> kk (+bias, +kk2T), y=1 -> vv. 512 threads: c = tid&255,
// half = tid>>8 splits the 256-long cp-sum in two; halves combined via smem.
__global__ void __launch_bounds__(512)
k_sty2(const float* __restrict__ sty, const float* __restrict__ timev,
       const float* __restrict__ sty_mask) {
    const int t    = blockIdx.x;         // 0..TP-1
    const int mat  = blockIdx.y;         // 0: kk, 1: vv
    const int tid  = threadIdx.x;
    const int c    = tid & 255;
    const int half = tid >> 8;
    const bool pad = (t >= T1);

    __shared__ __align__(16) float ss[Bb*Cc];     // s[b][cp]
    __shared__ __align__(16) float part[Bb*Cc];   // half-1 partials / bias scratch
    __shared__ float msk[Bb];

    if (tid < Bb) {
        float m = 1.0f;
        if (!pad && t > 0) m = sty_mask[tid*Tt + (t-1)];
        msk[tid] = m;
    }
    if (!pad) {
        for (int i = tid; i < Bb*Cc; i += 512) {
            int b = i >> 8, cp = i & 255;
            ss[i] = (t == 0) ? timev[b*Cc + cp]
                             : sty[((size_t)b*Cc + cp)*Tt + (t-1)];
        }
    }
    __syncthreads();

    float acc[Bb];
    #pragma unroll
    for (int b = 0; b < Bb; b++) acc[b] = 0.f;

    if (!pad) {
        const float* M = mat ? g_BmT : g_AT;
        const int cp0 = half * 128;
        for (int cp4 = 0; cp4 < 128; cp4 += 4) {
            float a0 = M[(cp0+cp4+0)*Cc + c];
            float a1 = M[(cp0+cp4+1)*Cc + c];
            float a2 = M[(cp0+cp4+2)*Cc + c];
            float a3 = M[(cp0+cp4+3)*Cc + c];
            #pragma unroll
            for (int b = 0; b < Bb; b++) {
                float4 sv = *(const float4*)&ss[b*Cc + cp0 + cp4];
                acc[b] = fmaf(a0, sv.x, acc[b]);
                acc[b] = fmaf(a1, sv.y, acc[b]);
                acc[b] = fmaf(a2, sv.z, acc[b]);
                acc[b] = fmaf(a3, sv.w, acc[b]);
            }
        }
    }

    // combine halves
    if (half) {
        #pragma unroll
        for (int b = 0; b < Bb; b++) part[b*Cc + c] = acc[b];
    }
    __syncthreads();
    if (!half) {
        #pragma unroll
        for (int b = 0; b < Bb; b++) acc[b] += part[b*Cc + c];
    }

    if (mat == 1) {
        if (!half) {
            #pragma unroll
            for (int b = 0; b < Bb; b++)
                g_vv[((size_t)b*TP + t)*Cc + c] = pad ? 0.f : acc[b];
        }
        return;   // all threads exit; no further barriers
    }

    // mat == 0: kk2 + bias
    float kk2[Bb];
    if (!half) {
        #pragma unroll
        for (int b = 0; b < Bb; b++) {
            float v = (!pad && msk[b] != 0.0f) ? acc[b] * g_rstd[b*Cc + c] : 0.f;
            kk2[b] = v;
            g_kk2T[((size_t)b*Cc + c)*TP + t] = v;
        }
    }
    __syncthreads();                       // part reads (above) done before overwrite
    if (!half) {
        #pragma unroll
        for (int b = 0; b < Bb; b++) part[b*Cc + c] = g_mean[b*Cc + c] * kk2[b];
    }
    __syncthreads();

    // 16 warps: warp w reduces batch b=w over 256 c
    int wp = tid >> 5, ln = tid & 31;
    float s = 0.f;
    #pragma unroll
    for (int k2 = 0; k2 < 8; k2++) s += part[wp*Cc + ln*8 + k2];
    #pragma unroll
    for (int o = 16; o > 0; o >>= 1) s += __shfl_xor_sync(0xffffffffu, s, o);
    if (ln == 0) {
        float bias = pad ? -1e30f : (msk[wp] == 0.0f ? -10000.0f : -s);
        g_bias[wp*TP + t] = bias;
    }
}

// ================= Kernel 4: fused attention main kernel =================
// Grid: (160, 16) = (h,wseg) x b. Block 256 threads, 128 px per CTA.
// ty = tid&15 (t-group of 9 / e-group), tx = tid>>4 (8 px: tx*8..tx*8+7).
// smem (floats): attn[144][130] | stage 2x2176 (x 8x128 + kk 8x144; vv 16x132) | bias[144] | xm[128]
#define XKBUF 2176
#define SM_STAGE_OFF (TP*ASTR)                    // 18720
#define SM_BIAS_OFF  (SM_STAGE_OFF + 2*XKBUF)     // 23072
#define SM_XM_OFF    (SM_BIAS_OFF + TP)           // 23216
#define SM_FLOATS    (SM_XM_OFF + PX)             // 23344 floats = 93.4 KB

__device__ __forceinline__ void fill_xk(uint32_t base, const float* xb,
                                        const float* kb, int c0, int tid) {
    // x: 8 rows x 128 floats = 256 float4 (exactly 1 per thread)
    cpa16(base + (((tid>>5)<<7) + ((tid&31)<<2))*4,
          xb + (size_t)(c0 + (tid>>5))*HW_ + ((tid&31)<<2));
    // kk2: 8 rows x 144 floats, contiguous source = 288 float4
    for (int i = tid; i < 288; i += 256)
        cpa16(base + (1024 + (i<<2))*4, kb + (size_t)c0*TP + (i<<2));
}

__device__ __forceinline__ void fill_v(uint32_t base, const float* vvb,
                                       int h, int tc, int tid) {
    #pragma unroll
    for (int r = 0; r < 2; r++) {
        int i = tid + r*256;
        int tt = i >> 5, col = i & 31;
        cpa16(base + (tt*132 + (col<<2))*4,
              vvb + (size_t)(tc*16 + tt)*Cc + h*128 + (col<<2));
    }
}

__global__ void __launch_bounds__(256, 2)
k_main(const float* __restrict__ x, const float* __restrict__ xmask,
       float* __restrict__ y) {
    extern __shared__ float smem[];
    float* attn  = smem;
    float* stage = smem + SM_STAGE_OFF;
    float* biasv = smem + SM_BIAS_OFF;
    float* xm    = smem + SM_XM_OFF;

    const int tile = blockIdx.x;          // 0..159
    const int b    = blockIdx.y;
    const int tid  = threadIdx.x;
    const int ty   = tid & 15;
    const int tx   = tid >> 4;
    const int w0   = (tile & 1) * PX;
    const int p0   = (tile >> 1) * Ww_ + w0;

    if (tid < TP) biasv[tid] = g_bias[b*TP + tid];
    if (tid < PX) xm[tid]    = xmask[b*Ww_ + w0 + tid];

    const float* xb  = x + (size_t)b*Cc*HW_ + p0;
    const float* kb  = g_kk2T + (size_t)b*Cc*TP;
    const float* vvb = g_vv   + (size_t)b*TP*Cc;
    const uint32_t stg = (uint32_t)__cvta_generic_to_shared(stage);

    // prefetch first x/k chunk (touches only stage region; safe before barrier)
    fill_xk(stg, xb, kb, 0, tid);
    CP_COMMIT();
    __syncthreads();                      // biasv/xm visible

    // -------- GEMM1: logits[px][t] = sum_c x[c][px]*kk2[c][t] + bias[t] --------
    unsigned long long acc[4][9];
    #pragma unroll
    for (int j = 0; j < 9; j++) {
        float bv = biasv[ty*9 + j];
        unsigned long long bp = pk2(bv, bv);
        #pragma unroll
        for (int i = 0; i < 4; i++) acc[i][j] = bp;
    }

    for (int s = 0; s < 32; s++) {
        CP_WAIT0();
        __syncthreads();
        if (s + 1 < 32) { fill_xk(stg + ((s+1)&1)*XKBUF*4, xb, kb, (s+1)*8, tid); CP_COMMIT(); }
        const float* xs = stage + (s&1)*XKBUF;
        const float* ks = xs + 1024;
        #pragma unroll
        for (int cc = 0; cc < 8; cc++) {
            const float* xr = xs + cc*128 + tx*8;
            unsigned long long xv[4];
            #pragma unroll
            for (int i = 0; i < 4; i++)
                xv[i] = *(const unsigned long long*)(xr + 2*i);
            const float* kr = ks + cc*144 + ty*9;
            #pragma unroll
            for (int j = 0; j < 9; j++) {
                float kvs = kr[j];
                unsigned long long kv = pk2(kvs, kvs);
                #pragma unroll
                for (int i = 0; i < 4; i++) FFMA2(acc[i][j], xv[i], kv);
            }
        }
    }

    // -------- softmax over t (144): shfl across the 16 ty-lanes --------
    float mx[8];
    #pragma unroll
    for (int i = 0; i < 8; i++) mx[i] = -3.4e38f;
    #pragma unroll
    for (int i = 0; i < 4; i++)
        #pragma unroll
        for (int j = 0; j < 9; j++) {
            float2 v = upk2(acc[i][j]);
            mx[2*i]   = fmaxf(mx[2*i],   v.x);
            mx[2*i+1] = fmaxf(mx[2*i+1], v.y);
        }
    #pragma unroll
    for (int s = 1; s < 16; s <<= 1)
        #pragma unroll
        for (int i = 0; i < 8; i++)
            mx[i] = fmaxf(mx[i], __shfl_xor_sync(0xffffffffu, mx[i], s));

    float sm[8];
    #pragma unroll
    for (int i = 0; i < 8; i++) sm[i] = 0.f;
    #pragma unroll
    for (int j = 0; j < 9; j++) {
        float* arow = attn + (ty*9 + j)*ASTR + tx*8;
        #pragma unroll
        for (int i = 0; i < 4; i++) {
            float2 v = upk2(acc[i][j]);
            float e0 = __expf(v.x - mx[2*i]);
            float e1 = __expf(v.y - mx[2*i+1]);
            sm[2*i]   += e0;
            sm[2*i+1] += e1;
            *(float2*)(arow + 2*i) = make_float2(e0, e1);
        }
    }
    #pragma unroll
    for (int s = 1; s < 16; s <<= 1)
        #pragma unroll
        for (int i = 0; i < 8; i++)
            sm[i] += __shfl_xor_sync(0xffffffffu, sm[i], s);

    unsigned long long rsp[4];
    #pragma unroll
    for (int i = 0; i < 4; i++)
        rsp[i] = pk2(1.0f / sm[2*i], 1.0f / sm[2*i+1]);

    // -------- GEMM2 + epilogue --------
    __syncthreads();                      // stage free + attn visible ordering start
    fill_v(stg, vvb, 0, 0, tid);
    CP_COMMIT();

    const size_t rowb = (size_t)b * Cc;

    for (int h = 0; h < 2; h++) {
        unsigned long long a2[4][8];
        #pragma unroll
        for (int i = 0; i < 4; i++)
            #pragma unroll
            for (int j = 0; j < 8; j++) a2[i][j] = 0ULL;

        for (int tc = 0; tc < 9; tc++) {
            int s2 = h*9 + tc;
            CP_WAIT0();
            __syncthreads();
            if (s2 + 1 < 18) {
                int ns = s2 + 1;
                fill_v(stg + (ns&1)*XKBUF*4, vvb, ns/9, ns%9, tid);
                CP_COMMIT();
            }
            const float* vs = stage + (s2&1)*XKBUF;
            #pragma unroll 4
            for (int tt = 0; tt < 16; tt++) {
                const float* arow = attn + (tc*16 + tt)*ASTR + tx*8;
                unsigned long long ap[4];
                #pragma unroll
                for (int i = 0; i < 4; i++)
                    ap[i] = *(const unsigned long long*)(arow + 2*i);
                const float* vr = vs + tt*132 + ty;
                #pragma unroll
                for (int j = 0; j < 8; j++) {
                    float vvv = vr[j*16];
                    unsigned long long vp = pk2(vvv, vvv);
                    #pragma unroll
                    for (int i = 0; i < 4; i++) FFMA2(a2[i][j], ap[i], vp);
                }
            }
        }

        // epilogue for this half: e = (h*8 + j)*16 + ty
        #pragma unroll
        for (int j = 0; j < 8; j++) {
            int e = (h*8 + j)*16 + ty;
            const float* xr = x + (rowb + e)*HW_ + p0 + tx*8;
            float*       yr = y + (rowb + e)*HW_ + p0 + tx*8;
            #pragma unroll
            for (int q = 0; q < 2; q++) {
                float2 o0 = upk2(mul2(a2[2*q  ][j], rsp[2*q  ]));
                float2 o1 = upk2(mul2(a2[2*q+1][j], rsp[2*q+1]));
                float4 xv = *(const float4*)(xr + 4*q);
                float4 m4 = *(const float4*)&xm[tx*8 + 4*q];
                float4 r;
                r.x = (xv.x + o0.x) * m4.x;
                r.y = (xv.y + o0.y) * m4.y;
                r.z = (xv.z + o1.x) * m4.z;
                r.w = (xv.w + o1.y) * m4.w;
                *(float4*)(yr + 4*q) = r;
            }
        }
    }
}

// ================= launch =================
extern "C" void kernel_launch(void* const* d_in, const int* in_sizes, int n_in,
                              void* d_out, int out_size) {
    const float* x        = (const float*)d_in[0];
    const float* x_mask   = (const float*)d_in[1];
    const float* sty      = (const float*)d_in[2];
    const float* sty_mask = (const float*)d_in[3];
    const float* timev    = (const float*)d_in[4];
    const float* Wq       = (const float*)d_in[5];
    const float* Wk       = (const float*)d_in[6];
    const float* Wv       = (const float*)d_in[7];
    const float* Wl       = (const float*)d_in[8];
    float* y = (float*)d_out;

    // stats (independent of prep kernels)
    k_stats<<<Bb*Cc, 256>>>(x);

    // folded weight matrices
    dim3 pb(16, 16), pg(16, 16);
    k_prepAT <<<pg, pb>>>(Wq, Wk);
    k_prepBmT<<<pg, pb>>>(Wl, Wv);

    // style projections: kk blocks and vv blocks in parallel
    k_sty2<<<dim3(TP, 2), 512>>>(sty, timev, sty_mask);

    // main fused kernel
    int smem_bytes = SM_FLOATS * (int)sizeof(float);
    cudaFuncSetAttribute(k_main, cudaFuncAttributeMaxDynamicSharedMemorySize, smem_bytes);
    dim3 grid(Hh * 2, Bb);
    k_main<<<grid, 256, smem_bytes>>>(x, x_mask, y);
}